// round 9
// baseline (speedup 1.0000x reference)
#include <cuda_runtime.h>
#include <cuda_fp16.h>
#include <math.h>

// Problem constants
#define BT 512      // batch
#define IC 1152     // in capsules
#define DD 8        // in dim
#define OC 10       // out capsules
#define EC 16       // out dim
#define G  4        // batches per CTA
#define T  512      // threads per CTA
#define NW 16       // warps
#define NCH 9       // chunks of 128 rows
#define RPC 128     // rows per chunk
#define LOG2E 1.4426950408889634f

typedef unsigned long long u64;

// Reordered fp16 W: [o][c(9)][j(4)][slot(512)][8 halves]
// slot = rl*4+eg; j = d-pair {2j,2j+1}; 8 halves = (d=2j: e01,e23), (d=2j+1: e01,e23)
__device__ __align__(16) __half Wh[(size_t)OC * IC * DD * EC];

__global__ void prep_kernel(const float* __restrict__ W) {
    int t = blockIdx.x * blockDim.x + threadIdx.x;   // < 184320
    int slot = t % 512;
    int r = t / 512;
    int j = r & 3; r >>= 2;
    int c = r % NCH;
    int o = r / NCH;
    int i = c * RPC + (slot >> 2);
    int eg = slot & 3;
    const float4* src = (const float4*)(W + ((size_t)o * IC + i) * 128);
    float4 a = src[(2 * j) * 4 + eg];       // d = 2j,   e = eg*4..+3
    float4 b = src[(2 * j + 1) * 4 + eg];   // d = 2j+1, e = eg*4..+3
    __half2 h[4];
    h[0] = __floats2half2_rn(a.x, a.y);
    h[1] = __floats2half2_rn(a.z, a.w);
    h[2] = __floats2half2_rn(b.x, b.y);
    h[3] = __floats2half2_rn(b.z, b.w);
    ((uint4*)Wh)[t] = *(uint4*)h;
}

// ---- packed fp32x2 helpers ----
__device__ __forceinline__ u64 pk2(float a, float b) {
    u64 r; asm("mov.b64 %0, {%1, %2};" : "=l"(r) : "f"(a), "f"(b)); return r;
}
__device__ __forceinline__ void fma2(u64& d, u64 a, u64 b) {
    asm("fma.rn.f32x2 %0, %1, %2, %3;" : "=l"(d) : "l"(a), "l"(b), "l"(d));
}
__device__ __forceinline__ float2 up2(u64 a) {
    float2 f; asm("mov.b64 {%0, %1}, %2;" : "=f"(f.x), "=f"(f.y) : "l"(a)); return f;
}
__device__ __forceinline__ float ex2f(float a) {
    float r; asm("ex2.approx.f32 %0, %1;" : "=f"(r) : "f"(a)); return r;
}

// One d-pair step: wv = 8 halves (d_even: e01,e23 | d_odd: e01,e23);
// xe[g]/xo[g] = x values at d_even/d_odd. A[g*2+h] += x*w for e-pair h.
__device__ __forceinline__ void dopair(u64* A, uint4 wv,
                                       const float* xe, const float* xo) {
    const __half2* hp = (const __half2*)&wv;
    float2 w0a = __half22float2(hp[0]);
    float2 w0b = __half22float2(hp[1]);
    float2 w1a = __half22float2(hp[2]);
    float2 w1b = __half22float2(hp[3]);
    u64 W0a = pk2(w0a.x, w0a.y), W0b = pk2(w0b.x, w0b.y);
    u64 W1a = pk2(w1a.x, w1a.y), W1b = pk2(w1b.x, w1b.y);
    #pragma unroll
    for (int g = 0; g < G; ++g) {
        u64 Xa = pk2(xe[g], xe[g]);
        u64 Xb = pk2(xo[g], xo[g]);
        fma2(A[g*2+0], Xa, W0a); fma2(A[g*2+0], Xb, W1a);
        fma2(A[g*2+1], Xa, W0b); fma2(A[g*2+1], Xb, W1b);
    }
}

__global__ __launch_bounds__(T, 1)
void caps_main(const float* __restrict__ x, float* __restrict__ out) {
    __shared__ float redv[G][NW][16];
    __shared__ float redz[G][NW];
    __shared__ float bc[G * 16];

    const int o   = blockIdx.y;
    const int b0  = blockIdx.x * G;
    const int tid = threadIdx.x;
    const int w    = tid >> 5;
    const int lane = tid & 31;
    const int rl   = tid >> 2;   // row within chunk (0..127)
    const int eg   = tid & 3;    // e-quarter

    const uint4* WoU = ((const uint4*)Wh) + (size_t)o * (NCH * 4 * T) + tid;
    const float* xbase = x + ((size_t)b0 * IC + rl) * DD;

    // Packed priors: P2[g][c*2 + h] = f32x2 (e = eg*4 + 2h, +1)
    u64 P2[G][NCH * 2];

    // ---------- Phase 1: W straight L2->regs, d-split halves ----------
    #pragma unroll
    for (int c = 0; c < NCH; ++c) {
        u64 A[G * 2];
        #pragma unroll
        for (int k = 0; k < G * 2; ++k) A[k] = 0;

        {   // d = 0..3 (j = 0,1)
            uint4 wa = WoU[(size_t)(c * 4 + 0) * T];
            uint4 wb = WoU[(size_t)(c * 4 + 1) * T];
            float4 xv[G];
            #pragma unroll
            for (int g = 0; g < G; ++g)
                xv[g] = *(const float4*)(xbase + (size_t)g * (IC * DD) + c * (RPC * DD));
            float xe[G], xo[G];
            #pragma unroll
            for (int g = 0; g < G; ++g) { xe[g] = xv[g].x; xo[g] = xv[g].y; }
            dopair(A, wa, xe, xo);
            #pragma unroll
            for (int g = 0; g < G; ++g) { xe[g] = xv[g].z; xo[g] = xv[g].w; }
            dopair(A, wb, xe, xo);
        }
        {   // d = 4..7 (j = 2,3)
            uint4 wa = WoU[(size_t)(c * 4 + 2) * T];
            uint4 wb = WoU[(size_t)(c * 4 + 3) * T];
            float4 xv[G];
            #pragma unroll
            for (int g = 0; g < G; ++g)
                xv[g] = *(const float4*)(xbase + (size_t)g * (IC * DD) + c * (RPC * DD) + 4);
            float xe[G], xo[G];
            #pragma unroll
            for (int g = 0; g < G; ++g) { xe[g] = xv[g].x; xo[g] = xv[g].y; }
            dopair(A, wa, xe, xo);
            #pragma unroll
            for (int g = 0; g < G; ++g) { xe[g] = xv[g].z; xo[g] = xv[g].w; }
            dopair(A, wb, xe, xo);
        }
        #pragma unroll
        for (int g = 0; g < G; ++g) {
            P2[g][c*2+0] = A[g*2+0];
            P2[g][c*2+1] = A[g*2+1];
        }
    }

    // ---------- Phase 2: routing (3 iterations, telescoped logits) ----------
    // iteration 0 (uniform probs): s = mean_i priors
    {
        const u64 ONE2 = pk2(1.f, 1.f);
        float q[G][4];
        #pragma unroll
        for (int g = 0; g < G; ++g) {
            u64 V0 = 0, V1 = 0;
            #pragma unroll
            for (int c = 0; c < NCH; ++c) {
                fma2(V0, P2[g][c*2+0], ONE2);
                fma2(V1, P2[g][c*2+1], ONE2);
            }
            float2 f;
            f = up2(V0); q[g][0] = f.x; q[g][1] = f.y;
            f = up2(V1); q[g][2] = f.x; q[g][3] = f.y;
        }
        #pragma unroll
        for (int off = 16; off >= 4; off >>= 1)
            #pragma unroll
            for (int g = 0; g < G; ++g)
                #pragma unroll
                for (int j = 0; j < 4; ++j)
                    q[g][j] += __shfl_down_sync(0xFFFFFFFFu, q[g][j], off);
        if (lane < 4)
            #pragma unroll
            for (int g = 0; g < G; ++g)
                #pragma unroll
                for (int j = 0; j < 4; ++j)
                    redv[g][w][lane * 4 + j] = q[g][j];
        __syncthreads();
        if (tid < G * 16) {
            const int g = tid >> 4;
            float s = 0.f;
            #pragma unroll
            for (int k = 0; k < NW; ++k) s += redv[g][k][tid & 15];
            s *= (1.f / (float)IC);
            float sq = s * s;
            sq += __shfl_xor_sync(0xFFFFFFFFu, sq, 1);
            sq += __shfl_xor_sync(0xFFFFFFFFu, sq, 2);
            sq += __shfl_xor_sync(0xFFFFFFFFu, sq, 4);
            sq += __shfl_xor_sync(0xFFFFFFFFu, sq, 8);
            float sc = sqrtf(sq) / (1.f + sq);
            bc[tid] = s * sc;
        }
        __syncthreads();
    }

    // iterations 1,2: dot against CUMULATIVE output (logits telescope),
    // exp via ex2 with log2e pre-folded into the cumulative op vector.
    float opf[G][4];
    #pragma unroll
    for (int g = 0; g < G; ++g)
        #pragma unroll
        for (int j = 0; j < 4; ++j) opf[g][j] = 0.f;

    #pragma unroll
    for (int iter = 1; iter <= 2; ++iter) {
        u64 OP[G][2];
        #pragma unroll
        for (int g = 0; g < G; ++g) {
            #pragma unroll
            for (int j = 0; j < 4; ++j)
                opf[g][j] = fmaf(bc[g * 16 + eg * 4 + j], LOG2E, opf[g][j]);
            OP[g][0] = pk2(opf[g][0], opf[g][1]);
            OP[g][1] = pk2(opf[g][2], opf[g][3]);
        }

        u64 S[G][2];
        float vz[G];
        #pragma unroll
        for (int g = 0; g < G; ++g) { S[g][0] = 0; S[g][1] = 0; vz[g] = 0.f; }

        #pragma unroll
        for (int c = 0; c < NCH; ++c) {
            #pragma unroll
            for (int g = 0; g < G; ++g) {
                u64 D = 0;
                fma2(D, P2[g][c*2+0], OP[g][0]);
                fma2(D, P2[g][c*2+1], OP[g][1]);
                float2 f = up2(D);
                float dp = f.x + f.y;
                dp += __shfl_xor_sync(0xFFFFFFFFu, dp, 1);
                dp += __shfl_xor_sync(0xFFFFFFFFu, dp, 2);
                float p = ex2f(dp);
                vz[g] += p;
                u64 PP = pk2(p, p);
                fma2(S[g][0], P2[g][c*2+0], PP);
                fma2(S[g][1], P2[g][c*2+1], PP);
            }
        }

        float s[G][4];
        #pragma unroll
        for (int g = 0; g < G; ++g) {
            float2 f;
            f = up2(S[g][0]); s[g][0] = f.x; s[g][1] = f.y;
            f = up2(S[g][1]); s[g][2] = f.x; s[g][3] = f.y;
        }
        #pragma unroll
        for (int off = 16; off >= 4; off >>= 1) {
            #pragma unroll
            for (int g = 0; g < G; ++g) {
                #pragma unroll
                for (int j = 0; j < 4; ++j)
                    s[g][j] += __shfl_down_sync(0xFFFFFFFFu, s[g][j], off);
                vz[g] += __shfl_down_sync(0xFFFFFFFFu, vz[g], off);
            }
        }
        if (lane < 4) {
            #pragma unroll
            for (int g = 0; g < G; ++g) {
                #pragma unroll
                for (int j = 0; j < 4; ++j)
                    redv[g][w][lane * 4 + j] = s[g][j];
                if (lane == 0) redz[g][w] = vz[g];
            }
        }
        __syncthreads();
        if (tid < G * 16) {
            const int g = tid >> 4;
            float sv = 0.f, Z = 0.f;
            #pragma unroll
            for (int k = 0; k < NW; ++k) {
                sv += redv[g][k][tid & 15];
                Z  += redz[g][k];
            }
            sv *= (1.f / Z);
            float sq = sv * sv;
            sq += __shfl_xor_sync(0xFFFFFFFFu, sq, 1);
            sq += __shfl_xor_sync(0xFFFFFFFFu, sq, 2);
            sq += __shfl_xor_sync(0xFFFFFFFFu, sq, 4);
            sq += __shfl_xor_sync(0xFFFFFFFFu, sq, 8);
            float sc = sqrtf(sq) / (1.f + sq);
            bc[tid] = sv * sc;
        }
        __syncthreads();
    }

    // final output: out[o, b0+g, 0, 0, e]
    if (tid < G * 16)
        out[((size_t)o * BT + (b0 + (tid >> 4))) * EC + (tid & 15)] = bc[tid];
}

extern "C" void kernel_launch(void* const* d_in, const int* in_sizes, int n_in,
                              void* d_out, int out_size) {
    const float* x = (const float*)d_in[0];   // [512,1152,8]
    const float* W = (const float*)d_in[1];   // [10,1152,8,16]
    float* out = (float*)d_out;               // [10,512,1,1,16]

    prep_kernel<<<720, 256>>>(W);

    dim3 grid(BT / G, OC);
    caps_main<<<grid, T>>>(x, out);
}

// round 10
// speedup vs baseline: 1.2795x; 1.2795x over previous
#include <cuda_runtime.h>
#include <cuda_fp16.h>
#include <math.h>

// Problem constants
#define BT 512      // batch
#define IC 1152     // in capsules
#define DD 8        // in dim
#define OC 10       // out capsules
#define EC 16       // out dim
#define G  2        // batches per CTA (register budget: P2 = G*NCH*2 u64 regs!)
#define T  512      // threads per CTA
#define NW 16       // warps
#define NCH 9       // chunks of 128 rows
#define RPC 128     // rows per chunk
#define LOG2E 1.4426950408889634f

typedef unsigned long long u64;

// Reordered fp16 W: [o][c(9)][j(4)][slot(512)][8 halves]
// slot = rl*4+eg; j = d-pair {2j,2j+1}; 8 halves = (d=2j: e01,e23), (d=2j+1: e01,e23)
__device__ __align__(16) __half Wh[(size_t)OC * IC * DD * EC];

__global__ void prep_kernel(const float* __restrict__ W) {
    int t = blockIdx.x * blockDim.x + threadIdx.x;   // < 184320
    int slot = t % 512;
    int r = t / 512;
    int j = r & 3; r >>= 2;
    int c = r % NCH;
    int o = r / NCH;
    int i = c * RPC + (slot >> 2);
    int eg = slot & 3;
    const float4* src = (const float4*)(W + ((size_t)o * IC + i) * 128);
    float4 a = src[(2 * j) * 4 + eg];       // d = 2j,   e = eg*4..+3
    float4 b = src[(2 * j + 1) * 4 + eg];   // d = 2j+1, e = eg*4..+3
    __half2 h[4];
    h[0] = __floats2half2_rn(a.x, a.y);
    h[1] = __floats2half2_rn(a.z, a.w);
    h[2] = __floats2half2_rn(b.x, b.y);
    h[3] = __floats2half2_rn(b.z, b.w);
    ((uint4*)Wh)[t] = *(uint4*)h;
}

// ---- packed fp32x2 helpers ----
__device__ __forceinline__ u64 pk2(float a, float b) {
    u64 r; asm("mov.b64 %0, {%1, %2};" : "=l"(r) : "f"(a), "f"(b)); return r;
}
__device__ __forceinline__ void fma2(u64& d, u64 a, u64 b) {
    asm("fma.rn.f32x2 %0, %1, %2, %3;" : "=l"(d) : "l"(a), "l"(b), "l"(d));
}
__device__ __forceinline__ float2 up2(u64 a) {
    float2 f; asm("mov.b64 {%0, %1}, %2;" : "=f"(f.x), "=f"(f.y) : "l"(a)); return f;
}
__device__ __forceinline__ float ex2f(float a) {
    float r; asm("ex2.approx.f32 %0, %1;" : "=f"(r) : "f"(a)); return r;
}

__global__ __launch_bounds__(T, 1)
void caps_main(const float* __restrict__ x, float* __restrict__ out) {
    __shared__ float redv[G][NW][16];
    __shared__ float redz[G][NW];
    __shared__ float bc[G * 16];

    const int o   = blockIdx.y;
    const int b0  = blockIdx.x * G;
    const int tid = threadIdx.x;
    const int w    = tid >> 5;
    const int lane = tid & 31;
    const int rl   = tid >> 2;   // row within chunk (0..127)
    const int eg   = tid & 3;    // e-quarter

    const uint4* WoU = ((const uint4*)Wh) + (size_t)o * (NCH * 4 * T) + tid;
    const float4* xp0 = (const float4*)(x + ((size_t)(b0 + 0) * IC + rl) * DD);
    const float4* xp1 = (const float4*)(x + ((size_t)(b0 + 1) * IC + rl) * DD);

    // Packed priors: P2[g][c*2 + h] = f32x2 pair (e = eg*4 + 2h, +1)  (72 regs)
    u64 P2[G][NCH * 2];

    // ------------- Phase 1: W straight L2->regs, no smem, no barriers -------------
    #pragma unroll
    for (int c = 0; c < NCH; ++c) {
        uint4 wv[4];
        #pragma unroll
        for (int j = 0; j < 4; ++j)
            wv[j] = WoU[(size_t)(c * 4 + j) * T];
        float4 x0a = xp0[c * 256], x0b = xp0[c * 256 + 1];
        float4 x1a = xp1[c * 256], x1b = xp1[c * 256 + 1];

        const float xg0[8] = {x0a.x, x0a.y, x0a.z, x0a.w, x0b.x, x0b.y, x0b.z, x0b.w};
        const float xg1[8] = {x1a.x, x1a.y, x1a.z, x1a.w, x1b.x, x1b.y, x1b.z, x1b.w};

        u64 A00 = 0, A01 = 0, A10 = 0, A11 = 0;  // [g][e-pair]
        #pragma unroll
        for (int j = 0; j < 4; ++j) {
            const __half2* hp = (const __half2*)&wv[j];
            float2 w0a = __half22float2(hp[0]);   // d=2j,   e01
            float2 w0b = __half22float2(hp[1]);   // d=2j,   e23
            float2 w1a = __half22float2(hp[2]);   // d=2j+1, e01
            float2 w1b = __half22float2(hp[3]);   // d=2j+1, e23
            u64 W0a = pk2(w0a.x, w0a.y), W0b = pk2(w0b.x, w0b.y);
            u64 W1a = pk2(w1a.x, w1a.y), W1b = pk2(w1b.x, w1b.y);
            u64 X0a = pk2(xg0[2*j],   xg0[2*j]);
            u64 X0b = pk2(xg0[2*j+1], xg0[2*j+1]);
            u64 X1a = pk2(xg1[2*j],   xg1[2*j]);
            u64 X1b = pk2(xg1[2*j+1], xg1[2*j+1]);
            fma2(A00, X0a, W0a); fma2(A00, X0b, W1a);
            fma2(A01, X0a, W0b); fma2(A01, X0b, W1b);
            fma2(A10, X1a, W0a); fma2(A10, X1b, W1a);
            fma2(A11, X1a, W0b); fma2(A11, X1b, W1b);
        }
        P2[0][c*2+0] = A00; P2[0][c*2+1] = A01;
        P2[1][c*2+0] = A10; P2[1][c*2+1] = A11;
    }

    // ---------------- Phase 2: routing, both g at once ----------------
    // ---- iteration 0 (uniform): s = mean_i priors (recomputed from P2) ----
    {
        const u64 ONE2 = pk2(1.f, 1.f);
        float q[G][4];
        #pragma unroll
        for (int g = 0; g < G; ++g) {
            u64 V0 = 0, V1 = 0;
            #pragma unroll
            for (int c = 0; c < NCH; ++c) {
                fma2(V0, P2[g][c*2+0], ONE2);
                fma2(V1, P2[g][c*2+1], ONE2);
            }
            float2 f;
            f = up2(V0); q[g][0] = f.x; q[g][1] = f.y;
            f = up2(V1); q[g][2] = f.x; q[g][3] = f.y;
        }
        #pragma unroll
        for (int off = 16; off >= 4; off >>= 1)
            #pragma unroll
            for (int g = 0; g < G; ++g)
                #pragma unroll
                for (int j = 0; j < 4; ++j)
                    q[g][j] += __shfl_down_sync(0xFFFFFFFFu, q[g][j], off);
        if (lane < 4)
            #pragma unroll
            for (int g = 0; g < G; ++g)
                #pragma unroll
                for (int j = 0; j < 4; ++j)
                    redv[g][w][lane * 4 + j] = q[g][j];
        __syncthreads();
        if (tid < G * 16) {
            const int g = tid >> 4;
            float s = 0.f;
            #pragma unroll
            for (int k = 0; k < NW; ++k) s += redv[g][k][tid & 15];
            s *= (1.f / (float)IC);
            float sq = s * s;
            sq += __shfl_xor_sync(0xFFFFFFFFu, sq, 1);
            sq += __shfl_xor_sync(0xFFFFFFFFu, sq, 2);
            sq += __shfl_xor_sync(0xFFFFFFFFu, sq, 4);
            sq += __shfl_xor_sync(0xFFFFFFFFu, sq, 8);
            float sc = sqrtf(sq) / (1.f + sq);
            bc[tid] = s * sc;
        }
        __syncthreads();
    }

    // ---- iterations 1,2: telescoped logits (dot vs CUMULATIVE output),
    //      exp = ex2(dot) with log2e folded into cumulative op vector ----
    float opf[G][4];
    #pragma unroll
    for (int g = 0; g < G; ++g)
        #pragma unroll
        for (int j = 0; j < 4; ++j) opf[g][j] = 0.f;

    #pragma unroll
    for (int iter = 1; iter <= 2; ++iter) {
        u64 OP[G][2];
        #pragma unroll
        for (int g = 0; g < G; ++g) {
            #pragma unroll
            for (int j = 0; j < 4; ++j)
                opf[g][j] = fmaf(bc[g * 16 + eg * 4 + j], LOG2E, opf[g][j]);
            OP[g][0] = pk2(opf[g][0], opf[g][1]);
            OP[g][1] = pk2(opf[g][2], opf[g][3]);
        }

        u64 S00 = 0, S01 = 0, S10 = 0, S11 = 0;
        float vz0 = 0.f, vz1 = 0.f;
        #pragma unroll
        for (int c = 0; c < NCH; ++c) {
            u64 D0 = 0, D1 = 0;
            fma2(D0, P2[0][c*2+0], OP[0][0]); fma2(D0, P2[0][c*2+1], OP[0][1]);
            fma2(D1, P2[1][c*2+0], OP[1][0]); fma2(D1, P2[1][c*2+1], OP[1][1]);
            float2 f0 = up2(D0), f1 = up2(D1);
            float dp0 = f0.x + f0.y;
            float dp1 = f1.x + f1.y;
            dp0 += __shfl_xor_sync(0xFFFFFFFFu, dp0, 1);
            dp1 += __shfl_xor_sync(0xFFFFFFFFu, dp1, 1);
            dp0 += __shfl_xor_sync(0xFFFFFFFFu, dp0, 2);
            dp1 += __shfl_xor_sync(0xFFFFFFFFu, dp1, 2);
            float p0 = ex2f(dp0);
            float p1 = ex2f(dp1);
            vz0 += p0; vz1 += p1;
            u64 PP0 = pk2(p0, p0), PP1 = pk2(p1, p1);
            fma2(S00, P2[0][c*2+0], PP0); fma2(S01, P2[0][c*2+1], PP0);
            fma2(S10, P2[1][c*2+0], PP1); fma2(S11, P2[1][c*2+1], PP1);
        }
        float s[G][4];
        float2 f;
        f = up2(S00); s[0][0] = f.x; s[0][1] = f.y;
        f = up2(S01); s[0][2] = f.x; s[0][3] = f.y;
        f = up2(S10); s[1][0] = f.x; s[1][1] = f.y;
        f = up2(S11); s[1][2] = f.x; s[1][3] = f.y;
        float vz[G] = {vz0, vz1};
        #pragma unroll
        for (int off = 16; off >= 4; off >>= 1) {
            #pragma unroll
            for (int g = 0; g < G; ++g) {
                #pragma unroll
                for (int j = 0; j < 4; ++j)
                    s[g][j] += __shfl_down_sync(0xFFFFFFFFu, s[g][j], off);
                vz[g] += __shfl_down_sync(0xFFFFFFFFu, vz[g], off);
            }
        }
        if (lane < 4) {
            #pragma unroll
            for (int g = 0; g < G; ++g) {
                #pragma unroll
                for (int j = 0; j < 4; ++j)
                    redv[g][w][lane * 4 + j] = s[g][j];
                if (lane == 0) redz[g][w] = vz[g];
            }
        }
        __syncthreads();
        if (tid < G * 16) {
            const int g = tid >> 4;
            float sv = 0.f, Z = 0.f;
            #pragma unroll
            for (int k = 0; k < NW; ++k) {
                sv += redv[g][k][tid & 15];
                Z  += redz[g][k];
            }
            sv *= (1.f / Z);
            float sq = sv * sv;
            sq += __shfl_xor_sync(0xFFFFFFFFu, sq, 1);
            sq += __shfl_xor_sync(0xFFFFFFFFu, sq, 2);
            sq += __shfl_xor_sync(0xFFFFFFFFu, sq, 4);
            sq += __shfl_xor_sync(0xFFFFFFFFu, sq, 8);
            float sc = sqrtf(sq) / (1.f + sq);
            bc[tid] = sv * sc;
        }
        __syncthreads();
    }

    // final output: out[o, b0+g, 0, 0, e]
    if (tid < G * 16)
        out[((size_t)o * BT + (b0 + (tid >> 4))) * EC + (tid & 15)] = bc[tid];
}

extern "C" void kernel_launch(void* const* d_in, const int* in_sizes, int n_in,
                              void* d_out, int out_size) {
    const float* x = (const float*)d_in[0];   // [512,1152,8]
    const float* W = (const float*)d_in[1];   // [10,1152,8,16]
    float* out = (float*)d_out;               // [10,512,1,1,16]

    prep_kernel<<<720, 256>>>(W);

    dim3 grid(BT / G, OC);
    caps_main<<<grid, T>>>(x, out);
}